// round 16
// baseline (speedup 1.0000x reference)
#include <cuda_runtime.h>
#include <cuda_bf16.h>
#include <math.h>
#include <float.h>
#include <stdint.h>

#define BATCH 2
#define CIN   256
#define SPT   131072
#define NB1   64
#define NTOK  16384
#define NCH   64
#define NK    64
#define TK    8
#define NTOKALL (BATCH * SPT)

// ---------------- scratch (device globals; allocation-free) ----------------
static __device__ float g_feat[(size_t)NB1 * NTOK * NCH];
static __device__ float g_val [(size_t)NB1 * NTOK * NCH];
static __device__ __nv_bfloat16 g_x1[(size_t)NTOKALL * 256];
static __device__ __nv_bfloat16 g_x2[(size_t)NTOKALL * 256];
static __device__ __nv_bfloat16 g_wv[2 * 256 * 256];   // value weights, split-2
static __device__ float g_cn [NB1 * NK * NCH];
static __device__ float g_vc [NB1 * NK * NCH];
static __device__ float g_cf [NB1 * NK * NCH];
static __device__ float g_cs [NB1 * NK * NCH];
static __device__ float g_den[NB1 * NK];
static __device__ float g_pcf[(size_t)NB1 * NK * 256];
static __device__ float g_aw [(size_t)NB1 * NTOK * TK];
static __device__ int   g_ai [(size_t)NB1 * NTOK * TK];

// ---------------- helpers ----------------
__device__ __forceinline__ uint32_t smem_u32(const void* p) {
    uint32_t a;
    asm("{ .reg .u64 t; cvta.to.shared.u64 t, %1; cvt.u32.u64 %0, t; }" : "=r"(a) : "l"(p));
    return a;
}
__device__ __forceinline__ void cpa16(uint32_t sa, const void* g) {
    asm volatile("{ .reg .u64 gg; cvta.to.global.u64 gg, %1; "
                 "cp.async.cg.shared.global [%0], [gg], 16; }"
                 :: "r"(sa), "l"(g) : "memory");
}
#define CP_COMMIT() asm volatile("cp.async.commit_group;" ::: "memory")

__device__ __forceinline__ void ldsm4(uint32_t addr, uint32_t* r) {
    asm volatile("ldmatrix.sync.aligned.m8n8.x4.shared.b16 {%0,%1,%2,%3}, [%4];"
                 : "=r"(r[0]), "=r"(r[1]), "=r"(r[2]), "=r"(r[3]) : "r"(addr));
}
__device__ __forceinline__ void mma16816(float* c, const uint32_t* a, const uint32_t* b) {
    asm volatile("mma.sync.aligned.m16n8k16.row.col.f32.bf16.bf16.f32 "
                 "{%0,%1,%2,%3}, {%4,%5,%6,%7}, {%8,%9}, {%0,%1,%2,%3};"
                 : "+f"(c[0]), "+f"(c[1]), "+f"(c[2]), "+f"(c[3])
                 : "r"(a[0]), "r"(a[1]), "r"(a[2]), "r"(a[3]), "r"(b[0]), "r"(b[1]));
}
__device__ __forceinline__ void split2(float v, __nv_bfloat16& a, __nv_bfloat16& b) {
    a = __float2bfloat16_rn(v);
    b = __float2bfloat16_rn(v - __bfloat162float(a));
}
__device__ __forceinline__ void ffma2(unsigned long long& d, unsigned long long a,
                                      unsigned long long b) {
    asm("fma.rn.f32x2 %0, %1, %2, %0;" : "+l"(d) : "l"(a), "l"(b));
}
__device__ __forceinline__ unsigned long long pack2(float lo, float hi) {
    unsigned long long r;
    asm("mov.b64 %0, {%1, %2};" : "=l"(r) : "f"(lo), "f"(hi));
    return r;
}
__device__ __forceinline__ void unpack2(unsigned long long v, float& lo, float& hi) {
    asm("mov.b64 {%0, %1}, %2;" : "=f"(lo), "=f"(hi) : "l"(v));
}

// ---------------------------------------------------------------------------
__global__ void zero_kernel() {
    int i = blockIdx.x * blockDim.x + threadIdx.x;
    if (i < NB1 * NK * NCH) g_cs[i] = 0.f;
    if (i < NB1 * NK) g_den[i] = 0.f;
}

__global__ void wsplit_kernel(const float* __restrict__ vw) {
    int i = blockIdx.x * 256 + threadIdx.x;
    if (i >= 65536) return;
    __nv_bfloat16 a, b;
    split2(vw[i], a, b);
    g_wv[i] = a;
    g_wv[65536 + i] = b;
}

// convertx v2 (R15): coalesced writes via padded smem staging
#define SMEM_CVT (256 * 33 * 4 + 2 * 32 * 264 * 2)
__global__ __launch_bounds__(256) void convertx_kernel(const float* __restrict__ x) {
    extern __shared__ char smc[];
    float* tile = (float*)smc;
    __nv_bfloat16* stg0 = (__nv_bfloat16*)(smc + 256 * 33 * 4);
    __nv_bfloat16* stg1 = stg0 + 32 * 264;
    const int b = blockIdx.y, s0 = blockIdx.x * 32, tid = threadIdx.x;
    for (int it = 0; it < 32; it++) {
        int idx = it * 256 + tid;
        int k = idx >> 5, sl = idx & 31;
        tile[k * 33 + sl] = x[((size_t)b * CIN + k) * SPT + s0 + sl];
    }
    __syncthreads();
    const int sl = tid & 31, kq = tid >> 5;
    __align__(16) __nv_bfloat16 p1[32], p2[32];
#pragma unroll
    for (int kk = 0; kk < 32; kk++)
        split2(tile[(kq * 32 + kk) * 33 + sl], p1[kk], p2[kk]);
#pragma unroll
    for (int u = 0; u < 4; u++) {
        *(uint4*)&stg0[sl * 264 + kq * 32 + u * 8] = ((const uint4*)p1)[u];
        *(uint4*)&stg1[sl * 264 + kq * 32 + u * 8] = ((const uint4*)p2)[u];
    }
    __syncthreads();
    size_t gb = ((size_t)(b * SPT + s0)) * 256;
#pragma unroll
    for (int ps = 0; ps < 4; ps++) {
        int row = ps * 8 + (tid >> 5);
        int col = (tid & 31) * 8;
        *(uint4*)(g_x1 + gb + row * 256 + col) = *(const uint4*)&stg0[row * 264 + col];
        *(uint4*)(g_x2 + gb + row * 256 + col) = *(const uint4*)&stg1[row * 264 + col];
    }
}

// ---------------------------------------------------------------------------
// COMBINED heavy kernel: interleaved block roles overlap the fma-bound SIMT
// feat conv with the tensor/mem-bound value HMMA GEMM on each SM.
// role = blockIdx.x & 1 : 0 -> conv_feat body (verbatim R11 numerics),
//                         1 -> value gemm body (verbatim R13).
// dynamic smem 81920 B (conv uses first 32768).
// ---------------------------------------------------------------------------
#define KC 16
#define STAGE_BYTES 40960
#define SMEM_HEAVY  (2 * STAGE_BYTES)

__device__ __forceinline__ void gemm_load_chunk(uint32_t sb, int stage,
                                                const __nv_bfloat16* const* Xp,
                                                const __nv_bfloat16* const* Wp,
                                                int k0, int tid) {
#pragma unroll
    for (int p = 0; p < 2; p++) {
#pragma unroll
        for (int it = 0; it < 2; it++) {
            int u = tid + it * 256;
            int r = u >> 2, c = u & 3;
            uint32_t base = sb + stage * STAGE_BYTES;
            cpa16(base + p * 10240 + r * 80 + c * 16, Xp[p] + (size_t)r * 256 + k0 + c * 8);
            cpa16(base + 20480 + p * 10240 + r * 80 + c * 16,
                  Wp[p] + (size_t)r * 256 + k0 + c * 8);
        }
    }
}

__global__ __launch_bounds__(256, 2) void heavy_kernel(
    const float* __restrict__ x, const float* __restrict__ fw,
    const float* __restrict__ fb, const float* __restrict__ vb) {
    extern __shared__ __align__(16) char smem[];
    const int tid = threadIdx.x;
    const int id = blockIdx.x;
    const int role = id & 1;
    const int sub = id >> 1;           // 0..4095
    const int b = sub >> 11;
    const int mb = (sub >> 1) & 1023;
    const int lo = sub & 1;            // conv: o-block, gemm: nb

    if (role == 0) {
        // ---------------- conv_feat body (bit-identical chains) -----------
        float (*As)[KC][128] = (float(*)[KC][128])smem;
        float (*Bs)[KC][128] = (float(*)[KC][128])(smem + 16384);
        const int o0 = lo * 128;
        const int s0 = mb * 128;
        const int tm = (tid & 15) << 3;
        const int tn = (tid >> 4) << 3;

        unsigned long long acc2[8][4];
        const unsigned long long z2 = pack2(0.f, 0.f);
#pragma unroll
        for (int i = 0; i < 8; i++)
#pragma unroll
            for (int j2 = 0; j2 < 4; j2++) acc2[i][j2] = z2;

        const int bn = tid & 127, kj0 = (tid >> 7) << 3;
        const float* wrow = fw + (size_t)(o0 + bn) * 256;
        const float* Ab = x + (size_t)b * CIN * SPT + s0;

        float4 bc0 = *(const float4*)(wrow + kj0);
        float4 bc1 = *(const float4*)(wrow + kj0 + 4);
        float4 bnx0, bnx1;
#pragma unroll
        for (int it = 0; it < 2; it++) {
            int u = tid + it * 256;
            int r = u >> 5, c = u & 31;
            cpa16(smem_u32(&As[0][r][c * 4]), Ab + (size_t)r * SPT + c * 4);
        }
        CP_COMMIT();

        for (int chk = 0; chk < 256 / KC; chk++) {
            const int cur = chk & 1;
            Bs[cur][kj0 + 0][bn] = bc0.x;
            Bs[cur][kj0 + 1][bn] = bc0.y;
            Bs[cur][kj0 + 2][bn] = bc0.z;
            Bs[cur][kj0 + 3][bn] = bc0.w;
            Bs[cur][kj0 + 4][bn] = bc1.x;
            Bs[cur][kj0 + 5][bn] = bc1.y;
            Bs[cur][kj0 + 6][bn] = bc1.z;
            Bs[cur][kj0 + 7][bn] = bc1.w;
            if (chk < 256 / KC - 1) {
                const int k0n = (chk + 1) * KC;
#pragma unroll
                for (int it = 0; it < 2; it++) {
                    int u = tid + it * 256;
                    int r = u >> 5, c = u & 31;
                    cpa16(smem_u32(&As[cur ^ 1][r][c * 4]),
                          Ab + (size_t)(k0n + r) * SPT + c * 4);
                }
                CP_COMMIT();
                bnx0 = *(const float4*)(wrow + k0n + kj0);
                bnx1 = *(const float4*)(wrow + k0n + kj0 + 4);
                asm volatile("cp.async.wait_group 1;" ::: "memory");
            } else {
                asm volatile("cp.async.wait_group 0;" ::: "memory");
            }
            __syncthreads();
#pragma unroll
            for (int k = 0; k < KC; k++) {
                float4 a0 = *(const float4*)&As[cur][k][tm];
                float4 a1 = *(const float4*)&As[cur][k][tm + 4];
                float4 b0 = *(const float4*)&Bs[cur][k][tn];
                float4 b1v = *(const float4*)&Bs[cur][k][tn + 4];
                unsigned long long bp[4];
                bp[0] = ((const unsigned long long*)&b0)[0];
                bp[1] = ((const unsigned long long*)&b0)[1];
                bp[2] = ((const unsigned long long*)&b1v)[0];
                bp[3] = ((const unsigned long long*)&b1v)[1];
                float av[8] = {a0.x, a0.y, a0.z, a0.w, a1.x, a1.y, a1.z, a1.w};
#pragma unroll
                for (int i = 0; i < 8; i++) {
                    unsigned long long ap = pack2(av[i], av[i]);
#pragma unroll
                    for (int j2 = 0; j2 < 4; j2++) ffma2(acc2[i][j2], ap, bp[j2]);
                }
            }
            __syncthreads();
            bc0 = bnx0;
            bc1 = bnx1;
        }

        float acc[8][8];
#pragma unroll
        for (int i = 0; i < 8; i++)
#pragma unroll
            for (int j2 = 0; j2 < 4; j2++)
                unpack2(acc2[i][j2], acc[i][2 * j2], acc[i][2 * j2 + 1]);

        int nArr[8], fbArr[8];
#pragma unroll
        for (int i = 0; i < 8; i++) {
            int s = s0 + tm + i;
            int d = s >> 12, h = (s >> 6) & 63, w = s & 63;
            fbArr[i] = ((d >> 4) << 2) | (((h >> 5) & 1) << 1) | ((w >> 5) & 1);
            nArr[i] = ((((d & 15) << 5) | (h & 31)) << 5) | (w & 31);
        }
#pragma unroll
        for (int j = 0; j < 8; j++) {
            int o = o0 + tn + j;
            float bias = fb[o];
            int e = o >> 6, c = o & 63;
            int hb = (b * 4 + e) << 3;
#pragma unroll
            for (int i = 0; i < 8; i++) {
                int b1 = hb | fbArr[i];
                g_feat[((size_t)b1 * NTOK + nArr[i]) * NCH + c] = acc[i][j] + bias;
            }
        }
    } else {
        // ---------------- value HMMA gemm body ---------------------------
        const uint32_t sb = smem_u32(smem);
        const int l = tid & 31, wid = tid >> 5;
        const int wm = wid >> 2, wn = wid & 3;
        const int nb = lo;
        const int tok0 = mb * 128;

        const __nv_bfloat16* Xp[2];
        const __nv_bfloat16* Wp[2];
        size_t xoff = ((size_t)b * SPT + tok0) * 256;
        Xp[0] = g_x1 + xoff;
        Xp[1] = g_x2 + xoff;
        for (int p = 0; p < 2; p++) Wp[p] = g_wv + (size_t)p * 65536 + (size_t)nb * 128 * 256;

        float acc[4][4][4];
#pragma unroll
        for (int i = 0; i < 4; i++)
#pragma unroll
            for (int j = 0; j < 4; j++)
#pragma unroll
                for (int q = 0; q < 4; q++) acc[i][j][q] = 0.f;

        gemm_load_chunk(sb, 0, Xp, Wp, 0, tid);
        CP_COMMIT();

        for (int ch = 0; ch < 8; ch++) {
            if (ch < 7) {
                gemm_load_chunk(sb, (ch + 1) & 1, Xp, Wp, (ch + 1) * 32, tid);
                CP_COMMIT();
                asm volatile("cp.async.wait_group 1;" ::: "memory");
            } else {
                asm volatile("cp.async.wait_group 0;" ::: "memory");
            }
            __syncthreads();
            uint32_t aw = sb + (ch & 1) * STAGE_BYTES + wm * 64 * 80;
            uint32_t bw = sb + (ch & 1) * STAGE_BYTES + 20480 + wn * 32 * 80;
#pragma unroll
            for (int ks = 0; ks < 2; ks++) {
                const int kb = ks * 32;
#pragma unroll
                for (int pa = 0; pa < 2; pa++) {
                    uint32_t a[4][4];
#pragma unroll
                    for (int i = 0; i < 4; i++)
                        ldsm4(aw + pa * 10240 + (i * 16 + (l & 15)) * 80 +
                                  ((l >> 4) << 4) + kb,
                              a[i]);
                    for (int pb = 0; pb < 2 - pa; pb++) {
                        uint32_t bq[2][4];
#pragma unroll
                        for (int jp = 0; jp < 2; jp++)
                            ldsm4(bw + pb * 10240 +
                                      (jp * 16 + ((l >> 4) << 3) + (l & 7)) * 80 +
                                      ((l >> 3) & 1) * 16 + kb,
                                  bq[jp]);
#pragma unroll
                        for (int i = 0; i < 4; i++)
#pragma unroll
                            for (int j = 0; j < 4; j++)
                                mma16816(acc[i][j], a[i], &bq[j >> 1][(j & 1) * 2]);
                    }
                }
            }
            __syncthreads();
        }

        int b1r[8], nr[8];
#pragma unroll
        for (int i = 0; i < 4; i++)
#pragma unroll
            for (int h = 0; h < 2; h++) {
                int t = tok0 + wm * 64 + i * 16 + (l >> 2) + h * 8;
                int d = t >> 12, hh = (t >> 6) & 63, ww = t & 63;
                b1r[i * 2 + h] = ((d >> 4) << 2) | (((hh >> 5) & 1) << 1) | ((ww >> 5) & 1);
                nr[i * 2 + h] = ((d & 15) << 10) | ((hh & 31) << 5) | (ww & 31);
            }
#pragma unroll
        for (int j = 0; j < 4; j++) {
            int o = nb * 128 + wn * 32 + j * 8 + 2 * (l & 3);
            int c = o & 63, e = o >> 6;
            float bi0 = __ldg(vb + o), bi1 = __ldg(vb + o + 1);
#pragma unroll
            for (int i = 0; i < 4; i++)
#pragma unroll
                for (int h = 0; h < 2; h++) {
                    int bb1 = (b * 4 + e) * 8 + b1r[i * 2 + h];
                    float2 v = make_float2(acc[i][j][h * 2] + bi0,
                                           acc[i][j][h * 2 + 1] + bi1);
                    *(float2*)&g_val[((size_t)bb1 * NTOK + nr[i * 2 + h]) * 64 + c] = v;
                }
        }
    }
}

// ---------------------------------------------------------------------------
__global__ __launch_bounds__(64) void centers_kernel() {
    const int b1 = blockIdx.x, k = blockIdx.y;
    const int c = threadIdx.x;
    const int pd = k >> 4, ph = (k >> 2) & 3, pw = k & 3;
    const float* fbase = g_feat + (size_t)b1 * NTOK * NCH;
    const float* vbase = g_val + (size_t)b1 * NTOK * NCH;
    float sf = 0.f, sv = 0.f;
    for (int di = 0; di < 4; di++)
        for (int hi = 0; hi < 8; hi++)
#pragma unroll
            for (int wi = 0; wi < 8; wi++) {
                int n = ((((pd * 4 + di) << 5) | (ph * 8 + hi)) << 5) | (pw * 8 + wi);
                size_t off = (size_t)n * NCH + c;
                sf += fbase[off];
                sv += vbase[off];
            }
    sf *= (1.f / 256.f);
    sv *= (1.f / 256.f);
    __shared__ float red[64];
    red[c] = sf * sf;
    for (int st = 32; st > 0; st >>= 1) {
        __syncthreads();
        if (c < st) red[c] += red[c + st];
    }
    __syncthreads();
    float rn = 1.f / fmaxf(sqrtf(red[0]), 1e-12f);
    size_t idx = ((size_t)b1 * NK + k) * NCH + c;
    g_cn[idx] = sf * rn;
    g_vc[idx] = sv;
}

// ---------------------------------------------------------------------------
#define SMEM_SIM 51200
__global__ __launch_bounds__(128) void sim_topk_kernel(
    const float* __restrict__ alpha_p, const float* __restrict__ beta_p) {
    const int b1 = blockIdx.y;
    const int n0 = blockIdx.x * 128;
    extern __shared__ float sm[];
    float* At = sm;
    float* Bc = sm + 64 * 132;
    __shared__ float invn_s[128];
    const int tid = threadIdx.x;
    const float alpha = alpha_p[0], beta = beta_p[0];

    {
        const float4* tp = (const float4*)(g_feat + ((size_t)b1 * NTOK + n0 + tid) * NCH);
        float ss = 0.f;
#pragma unroll
        for (int j = 0; j < 16; j++) {
            float4 t = tp[j];
            At[(j * 4 + 0) * 132 + tid] = t.x;
            At[(j * 4 + 1) * 132 + tid] = t.y;
            At[(j * 4 + 2) * 132 + tid] = t.z;
            At[(j * 4 + 3) * 132 + tid] = t.w;
            ss += t.x * t.x + t.y * t.y + t.z * t.z + t.w * t.w;
        }
        invn_s[tid] = 1.f / fmaxf(sqrtf(ss), 1e-12f);
    }
    {
        int k = tid >> 1, hf = tid & 1;
        const float4* cp = (const float4*)(g_cn + ((size_t)b1 * NK + k) * NCH + hf * 32);
#pragma unroll
        for (int j = 0; j < 8; j++) {
            float4 c4 = cp[j];
            int ch = hf * 32 + j * 4;
            Bc[(ch + 0) * 68 + k] = c4.x;
            Bc[(ch + 1) * 68 + k] = c4.y;
            Bc[(ch + 2) * 68 + k] = c4.z;
            Bc[(ch + 3) * 68 + k] = c4.w;
        }
    }
    __syncthreads();

    unsigned long long acc2[4][8];
    const unsigned long long z2 = pack2(0.f, 0.f);
#pragma unroll
    for (int i2 = 0; i2 < 4; i2++)
#pragma unroll
        for (int j = 0; j < 8; j++) acc2[i2][j] = z2;
    const int ta = (tid & 15) * 8, ca = (tid >> 4) * 8;
#pragma unroll 4
    for (int ch = 0; ch < 64; ch++) {
        float4 a0 = *(const float4*)&At[ch * 132 + ta];
        float4 a1 = *(const float4*)&At[ch * 132 + ta + 4];
        float4 b0 = *(const float4*)&Bc[ch * 68 + ca];
        float4 b1 = *(const float4*)&Bc[ch * 68 + ca + 4];
        unsigned long long ap[4];
        ap[0] = ((const unsigned long long*)&a0)[0];
        ap[1] = ((const unsigned long long*)&a0)[1];
        ap[2] = ((const unsigned long long*)&a1)[0];
        ap[3] = ((const unsigned long long*)&a1)[1];
        float bv[8] = {b0.x, b0.y, b0.z, b0.w, b1.x, b1.y, b1.z, b1.w};
#pragma unroll
        for (int j = 0; j < 8; j++) {
            unsigned long long bp = pack2(bv[j], bv[j]);
#pragma unroll
            for (int i2 = 0; i2 < 4; i2++) ffma2(acc2[i2][j], ap[i2], bp);
        }
    }
    __syncthreads();
    float* simS = sm;
#pragma unroll
    for (int i2 = 0; i2 < 4; i2++)
#pragma unroll
        for (int j = 0; j < 8; j++) {
            float lo, hi;
            unpack2(acc2[i2][j], lo, hi);
            simS[(ta + 2 * i2) * 65 + ca + j] = lo;
            simS[(ta + 2 * i2 + 1) * 65 + ca + j] = hi;
        }
    __syncthreads();

    const float invn = invn_s[tid];
    const float* srow = &simS[tid * 65];
    float bv[TK];
    int bi[TK];
#pragma unroll
    for (int j = 0; j < TK; j++) { bv[j] = -FLT_MAX; bi[j] = 0; }
    for (int k = 0; k < NK; k++) {
        float v = beta + alpha * (srow[k] * invn);
        v = v > 0.f ? v : 0.2f * v;
        if (v > bv[TK - 1]) {
            bv[TK - 1] = v;
            bi[TK - 1] = k;
#pragma unroll
            for (int p = TK - 1; p > 0; p--) {
                if (bv[p] > bv[p - 1]) {
                    float tv = bv[p]; bv[p] = bv[p - 1]; bv[p - 1] = tv;
                    int ti = bi[p]; bi[p] = bi[p - 1]; bi[p - 1] = ti;
                }
            }
        }
    }
    float m = bv[0];
    float e[TK], s = 0.f;
#pragma unroll
    for (int j = 0; j < TK; j++) { e[j] = expf(bv[j] - m); s += e[j]; }
    float rs = 1.f / s;
    float* awp = g_aw + ((size_t)b1 * NTOK + n0 + tid) * TK;
    int* aip = g_ai + ((size_t)b1 * NTOK + n0 + tid) * TK;
#pragma unroll
    for (int j = 0; j < TK; j++) { awp[j] = e[j] * rs; aip[j] = bi[j]; }
}

// ---------------------------------------------------------------------------
#define SMEM_SCAT (4 * NK * NCH * 4 + 4 * NK * 4)
__global__ __launch_bounds__(256) void scatter_kernel() {
    const int b1 = blockIdx.y;
    const int chunk = blockIdx.x;
    const int tid = threadIdx.x;
    const int g = tid >> 6, c = tid & 63;
    extern __shared__ float sm2[];
    float* acc = sm2;
    float* den = sm2 + 4 * NK * NCH;
    for (int i = tid; i < 4 * NK * NCH; i += 256) acc[i] = 0.f;
    for (int i = tid; i < 4 * NK; i += 256) den[i] = 0.f;
    __syncthreads();

    float* accg = acc + g * NK * NCH;
    float* deng = den + g * NK;
    const int t0 = chunk * 1024 + g * 256;
    const float* vb = g_val + (size_t)b1 * NTOK * NCH;
    const float* awb = g_aw + (size_t)b1 * NTOK * TK;
    const int* aib = g_ai + (size_t)b1 * NTOK * TK;
    for (int t = 0; t < 256; t++) {
        int n = t0 + t;
        float v = vb[(size_t)n * NCH + c];
#pragma unroll
        for (int j = 0; j < TK; j++) {
            float w = awb[(size_t)n * TK + j];
            int kk = aib[(size_t)n * TK + j];
            accg[kk * NCH + c] += w * v;
            if (kk == c) deng[c] += w;
        }
    }
    __syncthreads();
    float* csb = g_cs + (size_t)b1 * NK * NCH;
    for (int i = tid; i < NK * NCH; i += 256)
        atomicAdd(&csb[i], acc[i] + acc[NK * NCH + i] + acc[2 * NK * NCH + i] +
                               acc[3 * NK * NCH + i]);
    if (tid < NK)
        atomicAdd(&g_den[b1 * NK + tid],
                  den[tid] + den[NK + tid] + den[2 * NK + tid] + den[3 * NK + tid]);
}

__global__ void finalize_kernel() {
    int i = blockIdx.x * 256 + threadIdx.x;
    if (i < NB1 * NK * NCH) {
        float dn = fmaxf(g_den[i >> 6], 1e-6f);
        g_cf[i] = g_cs[i] / dn + g_vc[i];
    }
}

// ---------------------------------------------------------------------------
#define SMEM_PCF ((64 * 257 + 64 * 64) * 4)
__global__ __launch_bounds__(256) void pcf_kernel(const float* __restrict__ pw) {
    const int b1 = blockIdx.x;
    const int e = (b1 >> 3) & 3;
    extern __shared__ float smp[];
    float* pws = smp;
    float* cfs = smp + 64 * 257;
    const int tid = threadIdx.x;
    for (int u = tid; u < 16384; u += 256) {
        int o = u >> 6, c = u & 63;
        pws[c * 257 + o] = pw[o * 256 + e * 64 + c];
    }
    for (int u = tid; u < 4096; u += 256)
        cfs[u] = g_cf[(size_t)b1 * NK * NCH + u];
    __syncthreads();
    const int o = tid;
    for (int k = 0; k < 64; k++) {
        float a = 0.f;
#pragma unroll 8
        for (int c = 0; c < 64; c++) a += pws[c * 257 + o] * cfs[k * 64 + c];
        g_pcf[((size_t)b1 * NK + k) * 256 + o] = a;
    }
}

// ---------------------------------------------------------------------------
#define GP_PCF 32768
#define GP_OUT (64 * 132)
#define GP_AW  (4 * 64 * 8)
#define SMEM_GP ((GP_PCF + GP_OUT + 2 * GP_AW) * 4)
__global__ __launch_bounds__(256) void gproj_kernel(const float* __restrict__ pb_,
                                                    float* __restrict__ out) {
    const int part = blockIdx.x;
    const int fb = blockIdx.y, b = blockIdx.z;
    const int tid = threadIdx.x, warp = tid >> 5, lane = tid & 31;
    extern __shared__ float smg[];
    float* pcfs = smg;
    float* outs = smg + GP_PCF;
    float* aws  = outs + GP_OUT;
    int*   ais  = (int*)(aws + GP_AW);
    const int fd = fb >> 2, fh = (fb >> 1) & 1, fw = fb & 1;

    for (int oc = 0; oc < 2; oc++) {
        for (int u = tid; u < 256 * 32; u += 256) {
            int row = u >> 5, q = u & 31;
            int e = row >> 6, k = row & 63;
            int b1 = (b * 4 + e) * 8 + fb;
            cpa16(smem_u32(&pcfs[row * 128 + q * 4]),
                  g_pcf + ((size_t)(b1 * NK + k)) * 256 + oc * 128 + q * 4);
        }
        CP_COMMIT();
        asm volatile("cp.async.wait_group 0;" ::: "memory");
        __syncthreads();

        for (int sub = 0; sub < 4; sub++) {
            const int n0 = part * 256 + sub * 64;
            for (int u = tid; u < 512; u += 256) {
                int e = u >> 7, t2 = u & 127;
                int t = t2 >> 1, hf = t2 & 1;
                int b1 = (b * 4 + e) * 8 + fb;
                cpa16(smem_u32(&aws[(e * 64 + t) * 8 + hf * 4]),
                      g_aw + ((size_t)b1 * NTOK + n0 + t) * TK + hf * 4);
                cpa16(smem_u32(&ais[(e * 64 + t) * 8 + hf * 4]),
                      g_ai + ((size_t)b1 * NTOK + n0 + t) * TK + hf * 4);
            }
            CP_COMMIT();
            asm volatile("cp.async.wait_group 0;" ::: "memory");
            __syncthreads();
#pragma unroll
            for (int tt = 0; tt < 8; tt++) {
                int t = warp * 8 + tt;
                float4 acc = make_float4(0.f, 0.f, 0.f, 0.f);
#pragma unroll
                for (int e = 0; e < 4; e++) {
                    const float* wr = &aws[(e * 64 + t) * 8];
                    const int* kr = &ais[(e * 64 + t) * 8];
#pragma unroll
                    for (int j = 0; j < 8; j++) {
                        float w = wr[j];
                        int k = kr[j];
                        float4 p = *(const float4*)&pcfs[(e * 64 + k) * 128 + lane * 4];
                        acc.x += w * p.x;
                        acc.y += w * p.y;
                        acc.z += w * p.z;
                        acc.w += w * p.w;
                    }
                }
                *(float4*)&outs[t * 132 + lane * 4] = acc;
            }
            __syncthreads();
            int dd = n0 >> 10;
            int h0 = (n0 >> 5) & 31;
            size_t obase = (size_t)b * 256 * SPT;
            int sbase = (fd * 16 + dd) * 4096 + fw * 32;
#pragma unroll
            for (int it = 0; it < 16; it++) {
                int r = warp * 16 + it;
                int o = oc * 128 + r;
                float bias = __ldg(pb_ + o);
                float* op = out + obase + (size_t)o * SPT;
#pragma unroll
                for (int half = 0; half < 2; half++) {
                    int i = half * 32 + lane;
                    float v = outs[i * 132 + r] + bias;
                    int s = sbase + (fh * 32 + h0 + half) * 64 + lane;
                    op[s] = v;
                }
            }
            __syncthreads();
        }
    }
}

// ---------------------------------------------------------------------------
extern "C" void kernel_launch(void* const* d_in, const int* in_sizes, int n_in,
                              void* d_out, int out_size) {
    const float* x  = (const float*)d_in[0];
    const float* fw = (const float*)d_in[1];
    const float* fb = (const float*)d_in[2];
    const float* vw = (const float*)d_in[3];
    const float* vb = (const float*)d_in[4];
    const float* pw = (const float*)d_in[5];
    const float* pb = (const float*)d_in[6];
    const float* alpha = (const float*)d_in[7];
    const float* beta  = (const float*)d_in[8];
    float* out = (float*)d_out;

    cudaFuncSetAttribute(heavy_kernel, cudaFuncAttributeMaxDynamicSharedMemorySize, SMEM_HEAVY);
    cudaFuncSetAttribute(sim_topk_kernel, cudaFuncAttributeMaxDynamicSharedMemorySize, SMEM_SIM);
    cudaFuncSetAttribute(scatter_kernel, cudaFuncAttributeMaxDynamicSharedMemorySize, SMEM_SCAT);
    cudaFuncSetAttribute(pcf_kernel, cudaFuncAttributeMaxDynamicSharedMemorySize, SMEM_PCF);
    cudaFuncSetAttribute(gproj_kernel, cudaFuncAttributeMaxDynamicSharedMemorySize, SMEM_GP);
    cudaFuncSetAttribute(convertx_kernel, cudaFuncAttributeMaxDynamicSharedMemorySize, SMEM_CVT);

    zero_kernel<<<1024, 256>>>();
    wsplit_kernel<<<256, 256>>>(vw);
    convertx_kernel<<<dim3(SPT / 32, BATCH), 256, SMEM_CVT>>>(x);
    heavy_kernel<<<8192, 256, SMEM_HEAVY>>>(x, fw, fb, vb);
    centers_kernel<<<dim3(NB1, NK), 64>>>();
    sim_topk_kernel<<<dim3(NTOK / 128, NB1), 128, SMEM_SIM>>>(alpha, beta);
    scatter_kernel<<<dim3(16, NB1), 256, SMEM_SCAT>>>();
    finalize_kernel<<<1024, 256>>>();
    pcf_kernel<<<NB1, 256, SMEM_PCF>>>(pw);
    gproj_kernel<<<dim3(64, 8, BATCH), 256, SMEM_GP>>>(pb, out);
}

// round 17
// speedup vs baseline: 1.0310x; 1.0310x over previous
#include <cuda_runtime.h>
#include <cuda_bf16.h>
#include <math.h>
#include <float.h>
#include <stdint.h>

#define BATCH 2
#define CIN   256
#define SPT   131072
#define NB1   64
#define NTOK  16384
#define NCH   64
#define NK    64
#define TK    8

// ---------------- scratch (device globals; allocation-free) ----------------
static __device__ float g_feat[(size_t)NB1 * NTOK * NCH];
static __device__ float g_val [(size_t)NB1 * NTOK * NCH];
static __device__ __nv_bfloat16 g_wv[2 * 256 * 256];   // value weights, split-2
static __device__ float g_cn [NB1 * NK * NCH];
static __device__ float g_vc [NB1 * NK * NCH];
static __device__ float g_cf [NB1 * NK * NCH];
static __device__ float g_cs [NB1 * NK * NCH];
static __device__ float g_den[NB1 * NK];
static __device__ float g_pcf[(size_t)NB1 * NK * 256];
static __device__ float g_aw [(size_t)NB1 * NTOK * TK];
static __device__ int   g_ai [(size_t)NB1 * NTOK * TK];

// ---------------- helpers ----------------
__device__ __forceinline__ uint32_t smem_u32(const void* p) {
    uint32_t a;
    asm("{ .reg .u64 t; cvta.to.shared.u64 t, %1; cvt.u32.u64 %0, t; }" : "=r"(a) : "l"(p));
    return a;
}
__device__ __forceinline__ void cpa16(uint32_t sa, const void* g) {
    asm volatile("{ .reg .u64 gg; cvta.to.global.u64 gg, %1; "
                 "cp.async.cg.shared.global [%0], [gg], 16; }"
                 :: "r"(sa), "l"(g) : "memory");
}
#define CP_COMMIT() asm volatile("cp.async.commit_group;" ::: "memory")

__device__ __forceinline__ void ldsm4(uint32_t addr, uint32_t* r) {
    asm volatile("ldmatrix.sync.aligned.m8n8.x4.shared.b16 {%0,%1,%2,%3}, [%4];"
                 : "=r"(r[0]), "=r"(r[1]), "=r"(r[2]), "=r"(r[3]) : "r"(addr));
}
__device__ __forceinline__ void mma16816(float* c, const uint32_t* a, const uint32_t* b) {
    asm volatile("mma.sync.aligned.m16n8k16.row.col.f32.bf16.bf16.f32 "
                 "{%0,%1,%2,%3}, {%4,%5,%6,%7}, {%8,%9}, {%0,%1,%2,%3};"
                 : "+f"(c[0]), "+f"(c[1]), "+f"(c[2]), "+f"(c[3])
                 : "r"(a[0]), "r"(a[1]), "r"(a[2]), "r"(a[3]), "r"(b[0]), "r"(b[1]));
}
__device__ __forceinline__ void split2(float v, __nv_bfloat16& a, __nv_bfloat16& b) {
    a = __float2bfloat16_rn(v);
    b = __float2bfloat16_rn(v - __bfloat162float(a));
}
__device__ __forceinline__ void ffma2(unsigned long long& d, unsigned long long a,
                                      unsigned long long b) {
    asm("fma.rn.f32x2 %0, %1, %2, %0;" : "+l"(d) : "l"(a), "l"(b));
}
__device__ __forceinline__ unsigned long long pack2(float lo, float hi) {
    unsigned long long r;
    asm("mov.b64 %0, {%1, %2};" : "=l"(r) : "f"(lo), "f"(hi));
    return r;
}
__device__ __forceinline__ void unpack2(unsigned long long v, float& lo, float& hi) {
    asm("mov.b64 {%0, %1}, %2;" : "=f"(lo), "=f"(hi) : "l"(v));
}
__device__ __forceinline__ uint16_t bfbits(__nv_bfloat16 h) {
    return *(uint16_t*)&h;
}

// ---------------------------------------------------------------------------
__global__ void zero_kernel() {
    int i = blockIdx.x * blockDim.x + threadIdx.x;
    if (i < NB1 * NK * NCH) g_cs[i] = 0.f;
    if (i < NB1 * NK) g_den[i] = 0.f;
}

__global__ void wsplit_kernel(const float* __restrict__ vw) {
    int i = blockIdx.x * 256 + threadIdx.x;
    if (i >= 65536) return;
    __nv_bfloat16 a, b;
    split2(vw[i], a, b);
    g_wv[i] = a;
    g_wv[65536 + i] = b;
}

// ---------------------------------------------------------------------------
// FEAT conv: frozen winner (bit-identical k-ascending chains).
// ---------------------------------------------------------------------------
#define KC 16
__global__ __launch_bounds__(256, 2) void conv_feat_kernel(
    const float* __restrict__ x, const float* __restrict__ fw,
    const float* __restrict__ fb) {
    const int b  = blockIdx.z;
    const int o0 = blockIdx.x * 128;
    const int s0 = blockIdx.y * 128;
    __shared__ float As[2][KC][128];
    __shared__ float Bs[2][KC][128];
    const int tid = threadIdx.x;
    const int tm = (tid & 15) << 3;
    const int tn = (tid >> 4) << 3;

    unsigned long long acc2[8][4];
    const unsigned long long z2 = pack2(0.f, 0.f);
#pragma unroll
    for (int i = 0; i < 8; i++)
#pragma unroll
        for (int j2 = 0; j2 < 4; j2++) acc2[i][j2] = z2;

    const int bn = tid & 127, kj0 = (tid >> 7) << 3;
    const float* wrow = fw + (size_t)(o0 + bn) * 256;
    const float* Ab = x + (size_t)b * CIN * SPT + s0;

    float4 bc0 = *(const float4*)(wrow + kj0);
    float4 bc1 = *(const float4*)(wrow + kj0 + 4);
    float4 bnx0, bnx1;
#pragma unroll
    for (int it = 0; it < 2; it++) {
        int u = tid + it * 256;
        int r = u >> 5, c = u & 31;
        cpa16(smem_u32(&As[0][r][c * 4]), Ab + (size_t)r * SPT + c * 4);
    }
    CP_COMMIT();

    for (int chk = 0; chk < 256 / KC; chk++) {
        const int cur = chk & 1;
        Bs[cur][kj0 + 0][bn] = bc0.x;
        Bs[cur][kj0 + 1][bn] = bc0.y;
        Bs[cur][kj0 + 2][bn] = bc0.z;
        Bs[cur][kj0 + 3][bn] = bc0.w;
        Bs[cur][kj0 + 4][bn] = bc1.x;
        Bs[cur][kj0 + 5][bn] = bc1.y;
        Bs[cur][kj0 + 6][bn] = bc1.z;
        Bs[cur][kj0 + 7][bn] = bc1.w;
        if (chk < 256 / KC - 1) {
            const int k0n = (chk + 1) * KC;
#pragma unroll
            for (int it = 0; it < 2; it++) {
                int u = tid + it * 256;
                int r = u >> 5, c = u & 31;
                cpa16(smem_u32(&As[cur ^ 1][r][c * 4]),
                      Ab + (size_t)(k0n + r) * SPT + c * 4);
            }
            CP_COMMIT();
            bnx0 = *(const float4*)(wrow + k0n + kj0);
            bnx1 = *(const float4*)(wrow + k0n + kj0 + 4);
            asm volatile("cp.async.wait_group 1;" ::: "memory");
        } else {
            asm volatile("cp.async.wait_group 0;" ::: "memory");
        }
        __syncthreads();
#pragma unroll
        for (int k = 0; k < KC; k++) {
            float4 a0 = *(const float4*)&As[cur][k][tm];
            float4 a1 = *(const float4*)&As[cur][k][tm + 4];
            float4 b0 = *(const float4*)&Bs[cur][k][tn];
            float4 b1v = *(const float4*)&Bs[cur][k][tn + 4];
            unsigned long long bp[4];
            bp[0] = ((const unsigned long long*)&b0)[0];
            bp[1] = ((const unsigned long long*)&b0)[1];
            bp[2] = ((const unsigned long long*)&b1v)[0];
            bp[3] = ((const unsigned long long*)&b1v)[1];
            float av[8] = {a0.x, a0.y, a0.z, a0.w, a1.x, a1.y, a1.z, a1.w};
#pragma unroll
            for (int i = 0; i < 8; i++) {
                unsigned long long ap = pack2(av[i], av[i]);
#pragma unroll
                for (int j2 = 0; j2 < 4; j2++) ffma2(acc2[i][j2], ap, bp[j2]);
            }
        }
        __syncthreads();
        bc0 = bnx0;
        bc1 = bnx1;
    }

    float acc[8][8];
#pragma unroll
    for (int i = 0; i < 8; i++)
#pragma unroll
        for (int j2 = 0; j2 < 4; j2++)
            unpack2(acc2[i][j2], acc[i][2 * j2], acc[i][2 * j2 + 1]);

    int nArr[8], fbArr[8];
#pragma unroll
    for (int i = 0; i < 8; i++) {
        int s = s0 + tm + i;
        int d = s >> 12, h = (s >> 6) & 63, w = s & 63;
        fbArr[i] = ((d >> 4) << 2) | (((h >> 5) & 1) << 1) | ((w >> 5) & 1);
        nArr[i] = ((((d & 15) << 5) | (h & 31)) << 5) | (w & 31);
    }
#pragma unroll
    for (int j = 0; j < 8; j++) {
        int o = o0 + tn + j;
        float bias = fb[o];
        int e = o >> 6, c = o & 63;
        int hb = (b * 4 + e) << 3;
#pragma unroll
        for (int i = 0; i < 8; i++) {
            int b1 = hb | fbArr[i];
            g_feat[((size_t)b1 * NTOK + nArr[i]) * NCH + c] = acc[i][j] + bias;
        }
    }
}

// ---------------------------------------------------------------------------
// Value GEMM with IN-KERNEL split-2 conversion: reads x fp32 directly
// (coalesced 512B k-rows), converts to the 80B-row bf16 A-plane layout in
// smem, then the exact same HMMA sequence as before -> bit-identical g_val.
// smem: 2x fp32 staging (16896) + 2x B planes (20480) + A planes (20480)
//     = 95232 B, 2 blocks/SM.
// ---------------------------------------------------------------------------
#define GF_F(s) ((s) * 16896)
#define GF_B(s) (33792 + (s) * 20480)
#define GF_A    74752
#define SMEM_GEMM (GF_A + 20480)

__device__ __forceinline__ void gemm_load_chunk(uint32_t sb, int stage,
                                                const float* xbase,
                                                const __nv_bfloat16* const* Wp,
                                                int k0, int tid) {
    // fp32 A tile [32 k][128 tok] -> staging rows of 132 floats
#pragma unroll
    for (int it = 0; it < 4; it++) {
        int u = tid + it * 256;
        int r = u >> 5, c = u & 31;
        cpa16(sb + GF_F(stage) + r * 528 + c * 16, xbase + (size_t)(k0 + r) * SPT + c * 4);
    }
    // bf16 B planes (pre-split weights)
#pragma unroll
    for (int p = 0; p < 2; p++) {
#pragma unroll
        for (int it = 0; it < 2; it++) {
            int u = tid + it * 256;
            int r = u >> 2, c = u & 3;
            cpa16(sb + GF_B(stage) + p * 10240 + r * 80 + c * 16,
                  Wp[p] + (size_t)r * 256 + k0 + c * 8);
        }
    }
}

__global__ __launch_bounds__(256, 2) void gemm_kernel(const float* __restrict__ x,
                                                      const float* __restrict__ bias) {
    extern __shared__ __align__(16) char smem[];
    const uint32_t sb = smem_u32(smem);
    const int tid = threadIdx.x, l = tid & 31, wid = tid >> 5;
    const int wm = wid >> 2, wn = wid & 3;
    const int nb = blockIdx.x, mb = blockIdx.y, b = blockIdx.z;
    const int tok0 = mb * 128;

    const float* xbase = x + (size_t)b * CIN * SPT + tok0;
    const __nv_bfloat16* Wp[2];
    for (int p = 0; p < 2; p++) Wp[p] = g_wv + (size_t)p * 65536 + (size_t)nb * 128 * 256;

    float acc[4][4][4];
#pragma unroll
    for (int i = 0; i < 4; i++)
#pragma unroll
        for (int j = 0; j < 4; j++)
#pragma unroll
            for (int q = 0; q < 4; q++) acc[i][j][q] = 0.f;

    gemm_load_chunk(sb, 0, xbase, Wp, 0, tid);
    CP_COMMIT();

    const int tc = tid & 127;           // token column owned for conversion
    const int kh = (tid >> 7) * 16;     // k half (0 or 16)

    for (int ch = 0; ch < 8; ch++) {
        if (ch < 7) {
            gemm_load_chunk(sb, (ch + 1) & 1, xbase, Wp, (ch + 1) * 32, tid);
            CP_COMMIT();
            asm volatile("cp.async.wait_group 1;" ::: "memory");
        } else {
            asm volatile("cp.async.wait_group 0;" ::: "memory");
        }
        __syncthreads();
        // convert fp32 staging -> bf16 A planes (same split2 values as before)
        {
            const int cur = ch & 1;
            const float* sf = (const float*)(smem + GF_F(cur));
#pragma unroll
            for (int i = 0; i < 8; i++) {
                int k = kh + 2 * i;
                float f0 = sf[k * 132 + tc];
                float f1 = sf[(k + 1) * 132 + tc];
                __nv_bfloat16 a0, b0, a1, b1;
                split2(f0, a0, b0);
                split2(f1, a1, b1);
                uint32_t lo = (uint32_t)bfbits(a0) | ((uint32_t)bfbits(a1) << 16);
                uint32_t hi = (uint32_t)bfbits(b0) | ((uint32_t)bfbits(b1) << 16);
                *(uint32_t*)(smem + GF_A + tc * 80 + k * 2) = lo;
                *(uint32_t*)(smem + GF_A + 10240 + tc * 80 + k * 2) = hi;
            }
        }
        __syncthreads();
        uint32_t aw = sb + GF_A + wm * 64 * 80;
        uint32_t bw = sb + GF_B(ch & 1) + wn * 32 * 80;
#pragma unroll
        for (int ks = 0; ks < 2; ks++) {
            const int kb = ks * 32;
#pragma unroll
            for (int pa = 0; pa < 2; pa++) {
                uint32_t a[4][4];
#pragma unroll
                for (int i = 0; i < 4; i++)
                    ldsm4(aw + pa * 10240 + (i * 16 + (l & 15)) * 80 + ((l >> 4) << 4) + kb,
                          a[i]);
                for (int pb = 0; pb < 2 - pa; pb++) {
                    uint32_t bq[2][4];
#pragma unroll
                    for (int jp = 0; jp < 2; jp++)
                        ldsm4(bw + pb * 10240 + (jp * 16 + ((l >> 4) << 3) + (l & 7)) * 80 +
                                  ((l >> 3) & 1) * 16 + kb,
                              bq[jp]);
#pragma unroll
                    for (int i = 0; i < 4; i++)
#pragma unroll
                        for (int j = 0; j < 4; j++)
                            mma16816(acc[i][j], a[i], &bq[j >> 1][(j & 1) * 2]);
                }
            }
        }
        __syncthreads();
    }

    int b1r[8], nr[8];
#pragma unroll
    for (int i = 0; i < 4; i++)
#pragma unroll
        for (int h = 0; h < 2; h++) {
            int t = tok0 + wm * 64 + i * 16 + (l >> 2) + h * 8;
            int d = t >> 12, hh = (t >> 6) & 63, ww = t & 63;
            b1r[i * 2 + h] = ((d >> 4) << 2) | (((hh >> 5) & 1) << 1) | ((ww >> 5) & 1);
            nr[i * 2 + h] = ((d & 15) << 10) | ((hh & 31) << 5) | (ww & 31);
        }
#pragma unroll
    for (int j = 0; j < 4; j++) {
        int o = nb * 128 + wn * 32 + j * 8 + 2 * (l & 3);
        int c = o & 63, e = o >> 6;
        float bi0 = __ldg(bias + o), bi1 = __ldg(bias + o + 1);
#pragma unroll
        for (int i = 0; i < 4; i++)
#pragma unroll
            for (int h = 0; h < 2; h++) {
                int bb1 = (b * 4 + e) * 8 + b1r[i * 2 + h];
                float2 v = make_float2(acc[i][j][h * 2] + bi0, acc[i][j][h * 2 + 1] + bi1);
                *(float2*)&g_val[((size_t)bb1 * NTOK + nr[i * 2 + h]) * 64 + c] = v;
            }
    }
}

// ---------------------------------------------------------------------------
__global__ __launch_bounds__(64) void centers_kernel() {
    const int b1 = blockIdx.x, k = blockIdx.y;
    const int c = threadIdx.x;
    const int pd = k >> 4, ph = (k >> 2) & 3, pw = k & 3;
    const float* fbase = g_feat + (size_t)b1 * NTOK * NCH;
    const float* vbase = g_val + (size_t)b1 * NTOK * NCH;
    float sf = 0.f, sv = 0.f;
    for (int di = 0; di < 4; di++)
        for (int hi = 0; hi < 8; hi++)
#pragma unroll
            for (int wi = 0; wi < 8; wi++) {
                int n = ((((pd * 4 + di) << 5) | (ph * 8 + hi)) << 5) | (pw * 8 + wi);
                size_t off = (size_t)n * NCH + c;
                sf += fbase[off];
                sv += vbase[off];
            }
    sf *= (1.f / 256.f);
    sv *= (1.f / 256.f);
    __shared__ float red[64];
    red[c] = sf * sf;
    for (int st = 32; st > 0; st >>= 1) {
        __syncthreads();
        if (c < st) red[c] += red[c + st];
    }
    __syncthreads();
    float rn = 1.f / fmaxf(sqrtf(red[0]), 1e-12f);
    size_t idx = ((size_t)b1 * NK + k) * NCH + c;
    g_cn[idx] = sf * rn;
    g_vc[idx] = sv;
}

// ---------------------------------------------------------------------------
#define SMEM_SIM 51200
__global__ __launch_bounds__(128) void sim_topk_kernel(
    const float* __restrict__ alpha_p, const float* __restrict__ beta_p) {
    const int b1 = blockIdx.y;
    const int n0 = blockIdx.x * 128;
    extern __shared__ float sm[];
    float* At = sm;
    float* Bc = sm + 64 * 132;
    __shared__ float invn_s[128];
    const int tid = threadIdx.x;
    const float alpha = alpha_p[0], beta = beta_p[0];

    {
        const float4* tp = (const float4*)(g_feat + ((size_t)b1 * NTOK + n0 + tid) * NCH);
        float ss = 0.f;
#pragma unroll
        for (int j = 0; j < 16; j++) {
            float4 t = tp[j];
            At[(j * 4 + 0) * 132 + tid] = t.x;
            At[(j * 4 + 1) * 132 + tid] = t.y;
            At[(j * 4 + 2) * 132 + tid] = t.z;
            At[(j * 4 + 3) * 132 + tid] = t.w;
            ss += t.x * t.x + t.y * t.y + t.z * t.z + t.w * t.w;
        }
        invn_s[tid] = 1.f / fmaxf(sqrtf(ss), 1e-12f);
    }
    {
        int k = tid >> 1, hf = tid & 1;
        const float4* cp = (const float4*)(g_cn + ((size_t)b1 * NK + k) * NCH + hf * 32);
#pragma unroll
        for (int j = 0; j < 8; j++) {
            float4 c4 = cp[j];
            int ch = hf * 32 + j * 4;
            Bc[(ch + 0) * 68 + k] = c4.x;
            Bc[(ch + 1) * 68 + k] = c4.y;
            Bc[(ch + 2) * 68 + k] = c4.z;
            Bc[(ch + 3) * 68 + k] = c4.w;
        }
    }
    __syncthreads();

    unsigned long long acc2[4][8];
    const unsigned long long z2 = pack2(0.f, 0.f);
#pragma unroll
    for (int i2 = 0; i2 < 4; i2++)
#pragma unroll
        for (int j = 0; j < 8; j++) acc2[i2][j] = z2;
    const int ta = (tid & 15) * 8, ca = (tid >> 4) * 8;
#pragma unroll 4
    for (int ch = 0; ch < 64; ch++) {
        float4 a0 = *(const float4*)&At[ch * 132 + ta];
        float4 a1 = *(const float4*)&At[ch * 132 + ta + 4];
        float4 b0 = *(const float4*)&Bc[ch * 68 + ca];
        float4 b1 = *(const float4*)&Bc[ch * 68 + ca + 4];
        unsigned long long ap[4];
        ap[0] = ((const unsigned long long*)&a0)[0];
        ap[1] = ((const unsigned long long*)&a0)[1];
        ap[2] = ((const unsigned long long*)&a1)[0];
        ap[3] = ((const unsigned long long*)&a1)[1];
        float bv[8] = {b0.x, b0.y, b0.z, b0.w, b1.x, b1.y, b1.z, b1.w};
#pragma unroll
        for (int j = 0; j < 8; j++) {
            unsigned long long bp = pack2(bv[j], bv[j]);
#pragma unroll
            for (int i2 = 0; i2 < 4; i2++) ffma2(acc2[i2][j], ap[i2], bp);
        }
    }
    __syncthreads();
    float* simS = sm;
#pragma unroll
    for (int i2 = 0; i2 < 4; i2++)
#pragma unroll
        for (int j = 0; j < 8; j++) {
            float lo, hi;
            unpack2(acc2[i2][j], lo, hi);
            simS[(ta + 2 * i2) * 65 + ca + j] = lo;
            simS[(ta + 2 * i2 + 1) * 65 + ca + j] = hi;
        }
    __syncthreads();

    const float invn = invn_s[tid];
    const float* srow = &simS[tid * 65];
    float bv[TK];
    int bi[TK];
#pragma unroll
    for (int j = 0; j < TK; j++) { bv[j] = -FLT_MAX; bi[j] = 0; }
    for (int k = 0; k < NK; k++) {
        float v = beta + alpha * (srow[k] * invn);
        v = v > 0.f ? v : 0.2f * v;
        if (v > bv[TK - 1]) {
            bv[TK - 1] = v;
            bi[TK - 1] = k;
#pragma unroll
            for (int p = TK - 1; p > 0; p--) {
                if (bv[p] > bv[p - 1]) {
                    float tv = bv[p]; bv[p] = bv[p - 1]; bv[p - 1] = tv;
                    int ti = bi[p]; bi[p] = bi[p - 1]; bi[p - 1] = ti;
                }
            }
        }
    }
    float m = bv[0];
    float e[TK], s = 0.f;
#pragma unroll
    for (int j = 0; j < TK; j++) { e[j] = expf(bv[j] - m); s += e[j]; }
    float rs = 1.f / s;
    float* awp = g_aw + ((size_t)b1 * NTOK + n0 + tid) * TK;
    int* aip = g_ai + ((size_t)b1 * NTOK + n0 + tid) * TK;
#pragma unroll
    for (int j = 0; j < TK; j++) { awp[j] = e[j] * rs; aip[j] = bi[j]; }
}

// ---------------------------------------------------------------------------
#define SMEM_SCAT (4 * NK * NCH * 4 + 4 * NK * 4)
__global__ __launch_bounds__(256) void scatter_kernel() {
    const int b1 = blockIdx.y;
    const int chunk = blockIdx.x;
    const int tid = threadIdx.x;
    const int g = tid >> 6, c = tid & 63;
    extern __shared__ float sm2[];
    float* acc = sm2;
    float* den = sm2 + 4 * NK * NCH;
    for (int i = tid; i < 4 * NK * NCH; i += 256) acc[i] = 0.f;
    for (int i = tid; i < 4 * NK; i += 256) den[i] = 0.f;
    __syncthreads();

    float* accg = acc + g * NK * NCH;
    float* deng = den + g * NK;
    const int t0 = chunk * 1024 + g * 256;
    const float* vb = g_val + (size_t)b1 * NTOK * NCH;
    const float* awb = g_aw + (size_t)b1 * NTOK * TK;
    const int* aib = g_ai + (size_t)b1 * NTOK * TK;
    for (int t = 0; t < 256; t++) {
        int n = t0 + t;
        float v = vb[(size_t)n * NCH + c];
#pragma unroll
        for (int j = 0; j < TK; j++) {
            float w = awb[(size_t)n * TK + j];
            int kk = aib[(size_t)n * TK + j];
            accg[kk * NCH + c] += w * v;
            if (kk == c) deng[c] += w;
        }
    }
    __syncthreads();
    float* csb = g_cs + (size_t)b1 * NK * NCH;
    for (int i = tid; i < NK * NCH; i += 256)
        atomicAdd(&csb[i], acc[i] + acc[NK * NCH + i] + acc[2 * NK * NCH + i] +
                               acc[3 * NK * NCH + i]);
    if (tid < NK)
        atomicAdd(&g_den[b1 * NK + tid],
                  den[tid] + den[NK + tid] + den[2 * NK + tid] + den[3 * NK + tid]);
}

__global__ void finalize_kernel() {
    int i = blockIdx.x * 256 + threadIdx.x;
    if (i < NB1 * NK * NCH) {
        float dn = fmaxf(g_den[i >> 6], 1e-6f);
        g_cf[i] = g_cs[i] / dn + g_vc[i];
    }
}

// ---------------------------------------------------------------------------
#define SMEM_PCF ((64 * 257 + 64 * 64) * 4)
__global__ __launch_bounds__(256) void pcf_kernel(const float* __restrict__ pw) {
    const int b1 = blockIdx.x;
    const int e = (b1 >> 3) & 3;
    extern __shared__ float smp[];
    float* pws = smp;
    float* cfs = smp + 64 * 257;
    const int tid = threadIdx.x;
    for (int u = tid; u < 16384; u += 256) {
        int o = u >> 6, c = u & 63;
        pws[c * 257 + o] = pw[o * 256 + e * 64 + c];
    }
    for (int u = tid; u < 4096; u += 256)
        cfs[u] = g_cf[(size_t)b1 * NK * NCH + u];
    __syncthreads();
    const int o = tid;
    for (int k = 0; k < 64; k++) {
        float a = 0.f;
#pragma unroll 8
        for (int c = 0; c < 64; c++) a += pws[c * 257 + o] * cfs[k * 64 + c];
        g_pcf[((size_t)b1 * NK + k) * 256 + o] = a;
    }
}

// ---------------------------------------------------------------------------
#define GP_PCF 32768
#define GP_OUT (64 * 132)
#define GP_AW  (4 * 64 * 8)
#define SMEM_GP ((GP_PCF + GP_OUT + 2 * GP_AW) * 4)
__global__ __launch_bounds__(256) void gproj_kernel(const float* __restrict__ pb_,
                                                    float* __restrict__ out) {
    const int part = blockIdx.x;
    const int fb = blockIdx.y, b = blockIdx.z;
    const int tid = threadIdx.x, warp = tid >> 5, lane = tid & 31;
    extern __shared__ float smg[];
    float* pcfs = smg;
    float* outs = smg + GP_PCF;
    float* aws  = outs + GP_OUT;
    int*   ais  = (int*)(aws + GP_AW);
    const int fd = fb >> 2, fh = (fb >> 1) & 1, fw = fb & 1;

    for (int oc = 0; oc < 2; oc++) {
        for (int u = tid; u < 256 * 32; u += 256) {
            int row = u >> 5, q = u & 31;
            int e = row >> 6, k = row & 63;
            int b1 = (b * 4 + e) * 8 + fb;
            cpa16(smem_u32(&pcfs[row * 128 + q * 4]),
                  g_pcf + ((size_t)(b1 * NK + k)) * 256 + oc * 128 + q * 4);
        }
        CP_COMMIT();
        asm volatile("cp.async.wait_group 0;" ::: "memory");
        __syncthreads();

        for (int sub = 0; sub < 4; sub++) {
            const int n0 = part * 256 + sub * 64;
            for (int u = tid; u < 512; u += 256) {
                int e = u >> 7, t2 = u & 127;
                int t = t2 >> 1, hf = t2 & 1;
                int b1 = (b * 4 + e) * 8 + fb;
                cpa16(smem_u32(&aws[(e * 64 + t) * 8 + hf * 4]),
                      g_aw + ((size_t)b1 * NTOK + n0 + t) * TK + hf * 4);
                cpa16(smem_u32(&ais[(e * 64 + t) * 8 + hf * 4]),
                      g_ai + ((size_t)b1 * NTOK + n0 + t) * TK + hf * 4);
            }
            CP_COMMIT();
            asm volatile("cp.async.wait_group 0;" ::: "memory");
            __syncthreads();
#pragma unroll
            for (int tt = 0; tt < 8; tt++) {
                int t = warp * 8 + tt;
                float4 acc = make_float4(0.f, 0.f, 0.f, 0.f);
#pragma unroll
                for (int e = 0; e < 4; e++) {
                    const float* wr = &aws[(e * 64 + t) * 8];
                    const int* kr = &ais[(e * 64 + t) * 8];
#pragma unroll
                    for (int j = 0; j < 8; j++) {
                        float w = wr[j];
                        int k = kr[j];
                        float4 p = *(const float4*)&pcfs[(e * 64 + k) * 128 + lane * 4];
                        acc.x += w * p.x;
                        acc.y += w * p.y;
                        acc.z += w * p.z;
                        acc.w += w * p.w;
                    }
                }
                *(float4*)&outs[t * 132 + lane * 4] = acc;
            }
            __syncthreads();
            int dd = n0 >> 10;
            int h0 = (n0 >> 5) & 31;
            size_t obase = (size_t)b * 256 * SPT;
            int sbase = (fd * 16 + dd) * 4096 + fw * 32;
#pragma unroll
            for (int it = 0; it < 16; it++) {
                int r = warp * 16 + it;
                int o = oc * 128 + r;
                float bias = __ldg(pb_ + o);
                float* op = out + obase + (size_t)o * SPT;
#pragma unroll
                for (int half = 0; half < 2; half++) {
                    int i = half * 32 + lane;
                    float v = outs[i * 132 + r] + bias;
                    int s = sbase + (fh * 32 + h0 + half) * 64 + lane;
                    op[s] = v;
                }
            }
            __syncthreads();
        }
    }
}

// ---------------------------------------------------------------------------
extern "C" void kernel_launch(void* const* d_in, const int* in_sizes, int n_in,
                              void* d_out, int out_size) {
    const float* x  = (const float*)d_in[0];
    const float* fw = (const float*)d_in[1];
    const float* fb = (const float*)d_in[2];
    const float* vw = (const float*)d_in[3];
    const float* vb = (const float*)d_in[4];
    const float* pw = (const float*)d_in[5];
    const float* pb = (const float*)d_in[6];
    const float* alpha = (const float*)d_in[7];
    const float* beta  = (const float*)d_in[8];
    float* out = (float*)d_out;

    cudaFuncSetAttribute(gemm_kernel, cudaFuncAttributeMaxDynamicSharedMemorySize, SMEM_GEMM);
    cudaFuncSetAttribute(sim_topk_kernel, cudaFuncAttributeMaxDynamicSharedMemorySize, SMEM_SIM);
    cudaFuncSetAttribute(scatter_kernel, cudaFuncAttributeMaxDynamicSharedMemorySize, SMEM_SCAT);
    cudaFuncSetAttribute(pcf_kernel, cudaFuncAttributeMaxDynamicSharedMemorySize, SMEM_PCF);
    cudaFuncSetAttribute(gproj_kernel, cudaFuncAttributeMaxDynamicSharedMemorySize, SMEM_GP);

    zero_kernel<<<1024, 256>>>();
    wsplit_kernel<<<256, 256>>>(vw);
    conv_feat_kernel<<<dim3(2, SPT / 128, BATCH), 256>>>(x, fw, fb);
    gemm_kernel<<<dim3(2, SPT / 128, BATCH), 256, SMEM_GEMM>>>(x, vb);
    centers_kernel<<<dim3(NB1, NK), 64>>>();
    sim_topk_kernel<<<dim3(NTOK / 128, NB1), 128, SMEM_SIM>>>(alpha, beta);
    scatter_kernel<<<dim3(16, NB1), 256, SMEM_SCAT>>>();
    finalize_kernel<<<1024, 256>>>();
    pcf_kernel<<<NB1, 256, SMEM_PCF>>>(pw);
    gproj_kernel<<<dim3(64, 8, BATCH), 256, SMEM_GP>>>(pb, out);
}